// round 14
// baseline (speedup 1.0000x reference)
#include <cuda_runtime.h>
#include <cuda.h>
#include <cuda_fp16.h>
#include <cstdint>

// ---------------------------------------------------------------------------
// Problem dims
// ---------------------------------------------------------------------------
#define MDIM 8192
#define NDIM 4096
#define KDIM 4096

#if defined(__CUDA_ARCH_FEAT_SM103_ALL) || defined(__CUDA_ARCH_FEAT_SM100_ALL) || \
    (defined(__CUDA_ARCH_FAMILY_SPECIFIC__) && (__CUDA_ARCH_FAMILY_SPECIFIC__ >= 1000)) || \
    (defined(__CUDA_ARCH_SPECIFIC__) && (__CUDA_ARCH_SPECIFIC__ >= 1000))
#define TC_OK 1
#else
#define TC_OK 0
#endif

// Device scratch
__device__ __half g_Xh [(size_t)MDIM * (size_t)KDIM];   // fp16 X
__device__ __half g_Wth[(size_t)NDIM * (size_t)KDIM];   // fp16 K-major W

__device__ __forceinline__ uint32_t smem_u32(const void* p) {
    uint32_t a;
    asm("{ .reg .u64 t; cvta.to.shared.u64 t, %1; cvt.u32.u64 %0, t; }"
        : "=r"(a) : "l"(p));
    return a;
}
__device__ __forceinline__ float sigmoidf_fast(float z) {
    return 1.0f / (1.0f + __expf(-z));
}

// ---------------------------------------------------------------------------
// Fused conversion: X fp32->fp16 and W transpose-convert (one launch).
// ---------------------------------------------------------------------------
#define XBLKS ((int)(((size_t)MDIM * KDIM) / (256 * 8)))   // 16384
__global__ void __launch_bounds__(256) convert_all_kernel(
    const float* __restrict__ X, const float* __restrict__ W) {
    int b = blockIdx.x;
    if (b < XBLKS) {
        size_t i = ((size_t)b * 256 + threadIdx.x) * 8;
        float4 a = *reinterpret_cast<const float4*>(X + i);
        float4 c = *reinterpret_cast<const float4*>(X + i + 4);
        __half2* o = reinterpret_cast<__half2*>(g_Xh + i);
        o[0] = __floats2half2_rn(a.x, a.y);
        o[1] = __floats2half2_rn(a.z, a.w);
        o[2] = __floats2half2_rn(c.x, c.y);
        o[3] = __floats2half2_rn(c.z, c.w);
    } else {
        __shared__ float tile[32][33];
        int wb = b - XBLKS;
        int bx = (wb & 127) * 32;           // N block
        int by = (wb >> 7) * 32;            // K block
        int tx = threadIdx.x & 31, ty = threadIdx.x >> 5;
#pragma unroll
        for (int i = ty; i < 32; i += 8)
            tile[i][tx] = W[(size_t)(by + i) * NDIM + bx + tx];
        __syncthreads();
#pragma unroll
        for (int i = ty; i < 32; i += 8)
            g_Wth[(size_t)(bx + i) * KDIM + by + tx] = __float2half_rn(tile[tx][i]);
    }
}

// ===========================================================================
// Persistent cg2 fp16 tcgen05 GEMM (R13 champion, STAGES 6 -> 7).
// Grid = 148 CTAs (74 clusters). Cluster tile 256x256, BK=64, 7 stages.
// Warps 0-3: epilogue cols [0,128). Warp 4: TMA producer. Warp 5: MMA issuer.
// Warps 6-9: epilogue cols [128,256). Subpartition = wid&3 covers all rows.
// TMEM D double-buffered (cols 0/256); epilogue(t) overlaps mainloop(t+1).
// ===========================================================================
#define BM 128
#define BN 256
#define BNH 128
#define BK 64
#define NKB (KDIM / BK)             // 64
#define STAGES 7
#define STAGE_A_BYTES (BM * BK * 2)   // 16 KB
#define STAGE_B_BYTES (BNH * BK * 2)  // 16 KB
#define STAGE_BYTES   (STAGE_A_BYTES + STAGE_B_BYTES)      // 32 KB
#define FULL_TX_BYTES (2 * STAGE_BYTES)                    // 64 KB (pair)
#define SMEM_TILE0    1024
#define TC_SMEM_TOTAL (SMEM_TILE0 + STAGES * STAGE_BYTES)  // 230400

#define NCLUSTERS 74
#define NTILES    ((MDIM / 256) * (NDIM / 256))            // 512

#define OFF_TMEM     0
#define OFF_FULL(s)  (16 + (s) * 16)
#define OFF_FREE(s)  (24 + (s) * 16)
#define OFF_DONE(b)  (144 + (b) * 8)   // 144, 152
#define OFF_EPI(b)   (160 + (b) * 8)   // 160, 168

#if TC_OK
static constexpr uint32_t IDESC =
    (1u << 4) | ((BN / 8u) << 17) | ((256u / 16u) << 24);
static constexpr uint64_t DESC_BASE =
    (uint64_t(2) << 61) | (uint64_t(1) << 46) | (uint64_t(64) << 32) | (uint64_t(1) << 16);

__device__ __forceinline__ uint64_t make_desc(uint32_t addr) {
    return DESC_BASE | ((uint64_t)(addr >> 4) & 0x3FFF);
}

#define MBAR_INIT(a, c) \
    asm volatile("mbarrier.init.shared.b64 [%0], %1;" :: "r"(a), "r"(c) : "memory")
#define MBAR_EXPECT_TX(a, b) \
    asm volatile("mbarrier.arrive.expect_tx.shared.b64 _, [%0], %1;" :: "r"(a), "r"(b) : "memory")
#define MBAR_WAIT(a, p) do {                                                         \
    uint32_t _m = (a), _p = (p), _d;                                                 \
    asm volatile("{\n\t.reg .pred q;\n\t"                                            \
        "mbarrier.try_wait.parity.acquire.cta.shared::cta.b64 q, [%1], %2;\n\t"      \
        "selp.b32 %0, 1, 0, q;\n\t}"                                                 \
        : "=r"(_d) : "r"(_m), "r"(_p) : "memory");                                   \
    if (!_d) {                                                                       \
        asm volatile("{\n\t.reg .pred Q;\n\t"                                        \
            "WL%=:\n\t"                                                              \
            "mbarrier.try_wait.parity.acquire.cta.shared::cta.b64 Q, [%0], %1, 0x989680;\n\t" \
            "@Q bra WD%=;\n\t"                                                       \
            "bra WL%=;\n\t"                                                          \
            "WD%=:\n\t}" :: "r"(_m), "r"(_p) : "memory");                            \
    }                                                                                \
} while (0)
#define MBAR_WAIT_RELAXED(a, p) do {                                                 \
    uint32_t _m = (a), _p = (p), _d;                                                 \
    asm volatile("{\n\t.reg .pred q;\n\t"                                            \
        "mbarrier.try_wait.parity.relaxed.cta.shared::cta.b64 q, [%1], %2;\n\t"      \
        "selp.b32 %0, 1, 0, q;\n\t}"                                                 \
        : "=r"(_d) : "r"(_m), "r"(_p) : "memory");                                   \
    if (!_d) {                                                                       \
        asm volatile("{\n\t.reg .pred Q;\n\t"                                        \
            "WL%=:\n\t"                                                              \
            "mbarrier.try_wait.parity.relaxed.cta.shared::cta.b64 Q, [%0], %1, 0x989680;\n\t" \
            "@Q bra WD%=;\n\t"                                                       \
            "bra WL%=;\n\t"                                                          \
            "WD%=:\n\t}" :: "r"(_m), "r"(_p) : "memory");                            \
    }                                                                                \
} while (0)

#define CLUSTER_SYNC() do {                                             \
    asm volatile("barrier.cluster.arrive.aligned;" ::: "memory");       \
    asm volatile("barrier.cluster.wait.aligned;" ::: "memory");         \
} while (0)

// Arrive on the LEADER CTA's mbarrier at this smem offset (mapa to rank 0).
#define MBAR_ARRIVE_LEADER(a)                                                        \
    asm volatile("{\n\t.reg .b32 ra;\n\t"                                            \
        "mapa.shared::cluster.u32 ra, %0, 0;\n\t"                                    \
        "mbarrier.arrive.shared::cluster.b64 _, [ra];\n\t}"                          \
        :: "r"(a) : "memory")

#define TMA_LOAD_2D_CG2(dst, tm, cx, cy, mbar)                                       \
    asm volatile("{\n\t.reg .b32 lb;\n\t"                                            \
        "and.b32 lb, %4, 0xFEFFFFFF;\n\t"                                            \
        "cp.async.bulk.tensor.2d.cta_group::2.shared::cluster.global"                \
        ".tile.mbarrier::complete_tx::bytes [%0], [%1, {%2, %3}], [lb];\n\t}"        \
        :: "r"(dst), "l"(tm), "r"(cx), "r"(cy), "r"(mbar) : "memory")

__device__ __forceinline__ void mma_f16_cg2(uint32_t d, uint64_t ad, uint64_t bd,
                                            uint32_t idesc, uint32_t en) {
    asm volatile("{\n\t.reg .pred p;\n\t"
        "setp.ne.u32 p, %6, 0;\n\t"
        "tcgen05.mma.cta_group::2.kind::f16 [%0], %1, %2, %3, "
        "{%4, %4, %4, %4, %4, %4, %4, %4}, p;\n\t}"
        :: "r"(d), "l"(ad), "l"(bd), "r"(idesc), "r"(0u), "r"(0u), "r"(en)
        : "memory");
}

#define COMMIT_MC_CG2(bar)                                                           \
    asm volatile("tcgen05.commit.cta_group::2.mbarrier::arrive::one.shared::cluster" \
        ".multicast::cluster.b64 [%0], %1;" :: "r"(bar), "h"((uint16_t)0x3) : "memory")

#define LDTM_X32(r, addr)                                                            \
    asm volatile("tcgen05.ld.sync.aligned.32x32b.x32.b32 "                           \
        "{%0, %1, %2, %3, %4, %5, %6, %7, "                                          \
        " %8, %9, %10, %11, %12, %13, %14, %15, "                                    \
        " %16, %17, %18, %19, %20, %21, %22, %23, "                                  \
        " %24, %25, %26, %27, %28, %29, %30, %31}, [%32];"                           \
        : "=r"((r)[0]),  "=r"((r)[1]),  "=r"((r)[2]),  "=r"((r)[3]),                 \
          "=r"((r)[4]),  "=r"((r)[5]),  "=r"((r)[6]),  "=r"((r)[7]),                 \
          "=r"((r)[8]),  "=r"((r)[9]),  "=r"((r)[10]), "=r"((r)[11]),                \
          "=r"((r)[12]), "=r"((r)[13]), "=r"((r)[14]), "=r"((r)[15]),                \
          "=r"((r)[16]), "=r"((r)[17]), "=r"((r)[18]), "=r"((r)[19]),                \
          "=r"((r)[20]), "=r"((r)[21]), "=r"((r)[22]), "=r"((r)[23]),                \
          "=r"((r)[24]), "=r"((r)[25]), "=r"((r)[26]), "=r"((r)[27]),                \
          "=r"((r)[28]), "=r"((r)[29]), "=r"((r)[30]), "=r"((r)[31])                 \
        : "r"(addr))
#endif  // TC_OK

__global__ void __launch_bounds__(320, 1) __cluster_dims__(2, 1, 1) rbm_gemm_tc(
    const float* __restrict__ bias, float* __restrict__ C,
    const __grid_constant__ CUtensorMap tmaA,
    const __grid_constant__ CUtensorMap tmaB) {
#if TC_OK
    extern __shared__ char smem[];
    uint32_t sb = smem_u32(smem);
    int tid = threadIdx.x, wid = tid >> 5, lid = tid & 31;
    uint32_t rank;
    asm("mov.u32 %0, %%cluster_ctarank;" : "=r"(rank));
    int cluster_id = blockIdx.x >> 1;
    int ntiles = (NTILES - cluster_id + NCLUSTERS - 1) / NCLUSTERS;

    if (wid == 4) {
        asm volatile("tcgen05.alloc.cta_group::2.sync.aligned.shared::cta.b32 [%0], %1;"
                     :: "r"(sb + OFF_TMEM), "r"(512u) : "memory");
        asm volatile("tcgen05.relinquish_alloc_permit.cta_group::2.sync.aligned;");
    }
    if (tid == 0) {
#pragma unroll
        for (int s = 0; s < STAGES; s++) {
            MBAR_INIT(sb + OFF_FULL(s), 1);
            MBAR_INIT(sb + OFF_FREE(s), 1);
        }
        MBAR_INIT(sb + OFF_DONE(0), 1);
        MBAR_INIT(sb + OFF_DONE(1), 1);
        MBAR_INIT(sb + OFF_EPI(0), 2);
        MBAR_INIT(sb + OFF_EPI(1), 2);
    }
    __syncthreads();
    CLUSTER_SYNC();

    uint32_t tmem_base;
    asm volatile("ld.shared.b32 %0, [%1];" : "=r"(tmem_base) : "r"(sb + OFF_TMEM));

    if (wid == 4 && lid == 0) {
        // ---- Producer (both ranks): stream ALL tiles' k-blocks, ring never drains
        int s = 0, ph = 1;
        for (int t = 0; t < ntiles; t++) {
            int tile_id = cluster_id + t * NCLUSTERS;
            int m0 = (tile_id >> 4) * 256 + (int)rank * BM;
            int n0 = (tile_id & 15) * 256 + (int)rank * BNH;
            for (int kb = 0; kb < NKB; kb++) {
                MBAR_WAIT_RELAXED(sb + OFF_FREE(s), (uint32_t)ph);
                if (rank == 0)
                    MBAR_EXPECT_TX(sb + OFF_FULL(s), (uint32_t)FULL_TX_BYTES);
                uint32_t da = sb + SMEM_TILE0 + s * STAGE_BYTES;
                uint32_t db = da + STAGE_A_BYTES;
                int k0 = kb * BK;
                TMA_LOAD_2D_CG2(da, (const void*)&tmaA, k0, m0, sb + OFF_FULL(s));
                TMA_LOAD_2D_CG2(db, (const void*)&tmaB, k0, n0, sb + OFF_FULL(s));
                if (++s == STAGES) { s = 0; ph ^= 1; }
            }
        }
    } else if (wid == 5 && lid == 0 && rank == 0) {
        // ---- Leader MMA issuer
        int s = 0, ph = 0;
        for (int t = 0; t < ntiles; t++) {
            int b = t & 1, u = t >> 1;
            if (t >= 2)
                MBAR_WAIT(sb + OFF_EPI(b), (uint32_t)((u & 1) ^ 1));
            uint32_t dbuf = tmem_base + (uint32_t)b * 256;
            for (int kb = 0; kb < NKB; kb++) {
                MBAR_WAIT(sb + OFF_FULL(s), (uint32_t)ph);
                uint32_t sa = sb + SMEM_TILE0 + s * STAGE_BYTES;
                uint64_t ad = make_desc(sa);
                uint64_t bd = make_desc(sa + STAGE_A_BYTES);
                mma_f16_cg2(dbuf, ad,     bd,     IDESC, (kb > 0) ? 1u : 0u);
                mma_f16_cg2(dbuf, ad + 2, bd + 2, IDESC, 1u);
                mma_f16_cg2(dbuf, ad + 4, bd + 4, IDESC, 1u);
                mma_f16_cg2(dbuf, ad + 6, bd + 6, IDESC, 1u);
                COMMIT_MC_CG2(sb + OFF_FREE(s));
                if (++s == STAGES) { s = 0; ph ^= 1; }
            }
            COMMIT_MC_CG2(sb + OFF_DONE(b));
        }
    }

    if (wid < 4 || wid >= 6) {
        // ---- Epilogue: 8 warps. Group lo (wid 0-3) = cols [0,128),
        //      group hi (wid 6-9) = cols [128,256). Subpartition = wid&3.
        int cbase = (wid < 4) ? 0 : 128;
        int sub = wid & 3;
        for (int t = 0; t < ntiles; t++) {
            int b = t & 1, u = t >> 1;
            int tile_id = cluster_id + t * NCLUSTERS;
            MBAR_WAIT(sb + OFF_DONE(b), (uint32_t)(u & 1));
            asm volatile("tcgen05.fence::after_thread_sync;" ::: "memory");
            int row = (tile_id >> 4) * 256 + (int)rank * BM + sub * 32 + lid;
            int col0g = (tile_id & 15) * 256;
            float* crow = C + (size_t)row * NDIM + col0g;
            const float* brow = bias + col0g;
            uint32_t dbuf = tmem_base + (uint32_t)b * 256;
#pragma unroll
            for (int cc = 0; cc < 128; cc += 32) {
                int c0 = cbase + cc;
                uint32_t r[32];
                LDTM_X32(r, dbuf + c0);
                asm volatile("tcgen05.wait::ld.sync.aligned;" ::: "memory");
                float v[32];
#pragma unroll
                for (int i = 0; i < 32; i++) {
                    float z = __uint_as_float(r[i]) + __ldg(&brow[c0 + i]);
                    v[i] = sigmoidf_fast(z);
                }
#pragma unroll
                for (int q = 0; q < 8; q++) {
                    float4 o = make_float4(v[4 * q], v[4 * q + 1],
                                           v[4 * q + 2], v[4 * q + 3]);
                    reinterpret_cast<float4*>(crow + c0)[q] = o;
                }
            }
            asm volatile("tcgen05.fence::before_thread_sync;" ::: "memory");
            asm volatile("bar.sync 1, 256;" ::: "memory");   // 8 epi warps of this CTA
            if (tid == 0)
                MBAR_ARRIVE_LEADER(sb + OFF_EPI(b));          // 2 arrivals: one per CTA
        }
    }

    __syncthreads();
    if (wid == 4) {
        asm volatile("tcgen05.dealloc.cta_group::2.sync.aligned.b32 %0, %1;"
                     :: "r"(tmem_base), "r"(512u));
    }
    CLUSTER_SYNC();
#endif  // TC_OK
}

// ---------------------------------------------------------------------------
// Host launch
// ---------------------------------------------------------------------------
typedef CUresult (*PFN_encodeTiled)(
    CUtensorMap*, CUtensorMapDataType, cuuint32_t, void*,
    const cuuint64_t*, const cuuint64_t*, const cuuint32_t*, const cuuint32_t*,
    CUtensorMapInterleave, CUtensorMapSwizzle, CUtensorMapL2promotion,
    CUtensorMapFloatOOBfill);

extern "C" void kernel_launch(void* const* d_in, const int* in_sizes, int n_in,
                              void* d_out, int out_size) {
    const float* X    = (const float*)d_in[0];
    const float* W    = (const float*)d_in[1];
    const float* bias = (const float*)d_in[2];
    float* C = (float*)d_out;

    void *xh_ptr = nullptr, *wth_ptr = nullptr;
    cudaGetSymbolAddress(&xh_ptr, g_Xh);
    cudaGetSymbolAddress(&wth_ptr, g_Wth);

    convert_all_kernel<<<XBLKS + (NDIM / 32) * (KDIM / 32), 256>>>(X, W);

    PFN_encodeTiled encode = nullptr;
    cudaDriverEntryPointQueryResult qr;
    cudaGetDriverEntryPointByVersion("cuTensorMapEncodeTiled", (void**)&encode,
                                     12000, cudaEnableDefault, &qr);

    CUtensorMap tmaA, tmaB;
    if (encode) {
        cuuint64_t dimsA[2]   = {KDIM, MDIM};
        cuuint64_t strA[1]    = {(cuuint64_t)KDIM * sizeof(__half)};
        cuuint32_t boxA[2]    = {BK, BM};
        cuuint32_t es[2]      = {1, 1};
        encode(&tmaA, CU_TENSOR_MAP_DATA_TYPE_FLOAT16, 2, xh_ptr,
               dimsA, strA, boxA, es,
               CU_TENSOR_MAP_INTERLEAVE_NONE, CU_TENSOR_MAP_SWIZZLE_128B,
               CU_TENSOR_MAP_L2_PROMOTION_L2_128B, CU_TENSOR_MAP_FLOAT_OOB_FILL_NONE);
        cuuint64_t dimsB[2]   = {KDIM, NDIM};
        cuuint64_t strB[1]    = {(cuuint64_t)KDIM * sizeof(__half)};
        cuuint32_t boxB[2]    = {BK, BNH};
        encode(&tmaB, CU_TENSOR_MAP_DATA_TYPE_FLOAT16, 2, wth_ptr,
               dimsB, strB, boxB, es,
               CU_TENSOR_MAP_INTERLEAVE_NONE, CU_TENSOR_MAP_SWIZZLE_128B,
               CU_TENSOR_MAP_L2_PROMOTION_L2_128B, CU_TENSOR_MAP_FLOAT_OOB_FILL_NONE);
    }

    cudaFuncSetAttribute(rbm_gemm_tc,
                         cudaFuncAttributeMaxDynamicSharedMemorySize, TC_SMEM_TOTAL);
    // Persistent: 148 CTAs = 74 clusters of 2
    rbm_gemm_tc<<<dim3(2 * NCLUSTERS, 1), 320, TC_SMEM_TOTAL>>>(bias, C, tmaA, tmaB);
}

// round 15
// speedup vs baseline: 1.0284x; 1.0284x over previous
#include <cuda_runtime.h>
#include <cuda.h>
#include <cuda_fp16.h>
#include <cstdint>

// ---------------------------------------------------------------------------
// Problem dims
// ---------------------------------------------------------------------------
#define MDIM 8192
#define NDIM 4096
#define KDIM 4096

#if defined(__CUDA_ARCH_FEAT_SM103_ALL) || defined(__CUDA_ARCH_FEAT_SM100_ALL) || \
    (defined(__CUDA_ARCH_FAMILY_SPECIFIC__) && (__CUDA_ARCH_FAMILY_SPECIFIC__ >= 1000)) || \
    (defined(__CUDA_ARCH_SPECIFIC__) && (__CUDA_ARCH_SPECIFIC__ >= 1000))
#define TC_OK 1
#else
#define TC_OK 0
#endif

// Device scratch
__device__ __half g_Xh [(size_t)MDIM * (size_t)KDIM];   // fp16 X
__device__ __half g_Wth[(size_t)NDIM * (size_t)KDIM];   // fp16 K-major W

__device__ __forceinline__ uint32_t smem_u32(const void* p) {
    uint32_t a;
    asm("{ .reg .u64 t; cvta.to.shared.u64 t, %1; cvt.u32.u64 %0, t; }"
        : "=r"(a) : "l"(p));
    return a;
}
__device__ __forceinline__ float sigmoidf_fast(float z) {
    return 1.0f / (1.0f + __expf(-z));
}

// ---------------------------------------------------------------------------
// Fused conversion (one launch):
//  - blocks [0, XBLKS): X fp32 -> fp16, 8 elems/thread, float4 loads.
//  - blocks [XBLKS, XBLKS+8192): W[K][N] -> g_Wth[N][K] fp16 transpose,
//    32N x 64K tiles, [n][k] smem (conflict-free loads), __half2 packed
//    stores = 128B/warp coalesced along K.
// ---------------------------------------------------------------------------
#define XBLKS ((int)(((size_t)MDIM * KDIM) / (256 * 8)))   // 16384
#define WBLKS ((NDIM / 32) * (KDIM / 64))                  // 8192
__global__ void __launch_bounds__(256) convert_all_kernel(
    const float* __restrict__ X, const float* __restrict__ W) {
    int b = blockIdx.x;
    if (b < XBLKS) {
        size_t i = ((size_t)b * 256 + threadIdx.x) * 8;
        float4 a = *reinterpret_cast<const float4*>(X + i);
        float4 c = *reinterpret_cast<const float4*>(X + i + 4);
        __half2* o = reinterpret_cast<__half2*>(g_Xh + i);
        o[0] = __floats2half2_rn(a.x, a.y);
        o[1] = __floats2half2_rn(a.z, a.w);
        o[2] = __floats2half2_rn(c.x, c.y);
        o[3] = __floats2half2_rn(c.z, c.w);
    } else {
        __shared__ float tile[32][65];      // [n][k], 65 stride: CF loads
        int wb = b - XBLKS;
        int bx = (wb & 127) * 32;           // N block (128 per row)
        int by = (wb >> 7) * 64;            // K block (64 rows of 64)
        int t = threadIdx.x;
        // Load 64K x 32N fp32: each thread 8 elems, rows of 32 floats coalesced
#pragma unroll
        for (int i = 0; i < 8; i++) {
            int idx = t + i * 256;
            int k = idx >> 5, n = idx & 31;
            tile[n][k] = W[(size_t)(by + k) * NDIM + bx + n];
        }
        __syncthreads();
        // Store: warp g handles n = g, g+8, g+16, g+24; lane = K-pair index.
        int lane = t & 31, g = t >> 5;
#pragma unroll
        for (int j = 0; j < 4; j++) {
            int n = g + j * 8;
            __half2 h = __floats2half2_rn(tile[n][2 * lane], tile[n][2 * lane + 1]);
            *reinterpret_cast<__half2*>(
                &g_Wth[(size_t)(bx + n) * KDIM + by + 2 * lane]) = h;
        }
    }
}

// ===========================================================================
// Persistent cg2 fp16 tcgen05 GEMM (R13 champion: 6 stages, 8-warp epilogue).
// Grid = 148 CTAs (74 clusters). Cluster tile 256x256, BK=64.
// Warps 0-3: epilogue cols [0,128). Warp 4: TMA producer. Warp 5: MMA issuer.
// Warps 6-9: epilogue cols [128,256). Subpartition = wid&3 covers all rows.
// TMEM D double-buffered (cols 0/256); epilogue(t) overlaps mainloop(t+1).
// ===========================================================================
#define BM 128
#define BN 256
#define BNH 128
#define BK 64
#define NKB (KDIM / BK)             // 64
#define STAGES 6
#define STAGE_A_BYTES (BM * BK * 2)   // 16 KB
#define STAGE_B_BYTES (BNH * BK * 2)  // 16 KB
#define STAGE_BYTES   (STAGE_A_BYTES + STAGE_B_BYTES)      // 32 KB
#define FULL_TX_BYTES (2 * STAGE_BYTES)                    // 64 KB (pair)
#define SMEM_TILE0    1024
#define TC_SMEM_TOTAL (SMEM_TILE0 + STAGES * STAGE_BYTES)  // 197632

#define NCLUSTERS 74
#define NTILES    ((MDIM / 256) * (NDIM / 256))            // 512

#define OFF_TMEM     0
#define OFF_FULL(s)  (16 + (s) * 16)
#define OFF_FREE(s)  (24 + (s) * 16)
#define OFF_DONE(b)  (128 + (b) * 8)   // 128, 136
#define OFF_EPI(b)   (144 + (b) * 8)   // 144, 152

#if TC_OK
static constexpr uint32_t IDESC =
    (1u << 4) | ((BN / 8u) << 17) | ((256u / 16u) << 24);
static constexpr uint64_t DESC_BASE =
    (uint64_t(2) << 61) | (uint64_t(1) << 46) | (uint64_t(64) << 32) | (uint64_t(1) << 16);

__device__ __forceinline__ uint64_t make_desc(uint32_t addr) {
    return DESC_BASE | ((uint64_t)(addr >> 4) & 0x3FFF);
}

#define MBAR_INIT(a, c) \
    asm volatile("mbarrier.init.shared.b64 [%0], %1;" :: "r"(a), "r"(c) : "memory")
#define MBAR_EXPECT_TX(a, b) \
    asm volatile("mbarrier.arrive.expect_tx.shared.b64 _, [%0], %1;" :: "r"(a), "r"(b) : "memory")
#define MBAR_WAIT(a, p) do {                                                         \
    uint32_t _m = (a), _p = (p), _d;                                                 \
    asm volatile("{\n\t.reg .pred q;\n\t"                                            \
        "mbarrier.try_wait.parity.acquire.cta.shared::cta.b64 q, [%1], %2;\n\t"      \
        "selp.b32 %0, 1, 0, q;\n\t}"                                                 \
        : "=r"(_d) : "r"(_m), "r"(_p) : "memory");                                   \
    if (!_d) {                                                                       \
        asm volatile("{\n\t.reg .pred Q;\n\t"                                        \
            "WL%=:\n\t"                                                              \
            "mbarrier.try_wait.parity.acquire.cta.shared::cta.b64 Q, [%0], %1, 0x989680;\n\t" \
            "@Q bra WD%=;\n\t"                                                       \
            "bra WL%=;\n\t"                                                          \
            "WD%=:\n\t}" :: "r"(_m), "r"(_p) : "memory");                            \
    }                                                                                \
} while (0)
#define MBAR_WAIT_RELAXED(a, p) do {                                                 \
    uint32_t _m = (a), _p = (p), _d;                                                 \
    asm volatile("{\n\t.reg .pred q;\n\t"                                            \
        "mbarrier.try_wait.parity.relaxed.cta.shared::cta.b64 q, [%1], %2;\n\t"      \
        "selp.b32 %0, 1, 0, q;\n\t}"                                                 \
        : "=r"(_d) : "r"(_m), "r"(_p) : "memory");                                   \
    if (!_d) {                                                                       \
        asm volatile("{\n\t.reg .pred Q;\n\t"                                        \
            "WL%=:\n\t"                                                              \
            "mbarrier.try_wait.parity.relaxed.cta.shared::cta.b64 Q, [%0], %1, 0x989680;\n\t" \
            "@Q bra WD%=;\n\t"                                                       \
            "bra WL%=;\n\t"                                                          \
            "WD%=:\n\t}" :: "r"(_m), "r"(_p) : "memory");                            \
    }                                                                                \
} while (0)

#define CLUSTER_SYNC() do {                                             \
    asm volatile("barrier.cluster.arrive.aligned;" ::: "memory");       \
    asm volatile("barrier.cluster.wait.aligned;" ::: "memory");         \
} while (0)

// Arrive on the LEADER CTA's mbarrier at this smem offset (mapa to rank 0).
#define MBAR_ARRIVE_LEADER(a)                                                        \
    asm volatile("{\n\t.reg .b32 ra;\n\t"                                            \
        "mapa.shared::cluster.u32 ra, %0, 0;\n\t"                                    \
        "mbarrier.arrive.shared::cluster.b64 _, [ra];\n\t}"                          \
        :: "r"(a) : "memory")

#define TMA_LOAD_2D_CG2(dst, tm, cx, cy, mbar)                                       \
    asm volatile("{\n\t.reg .b32 lb;\n\t"                                            \
        "and.b32 lb, %4, 0xFEFFFFFF;\n\t"                                            \
        "cp.async.bulk.tensor.2d.cta_group::2.shared::cluster.global"                \
        ".tile.mbarrier::complete_tx::bytes [%0], [%1, {%2, %3}], [lb];\n\t}"        \
        :: "r"(dst), "l"(tm), "r"(cx), "r"(cy), "r"(mbar) : "memory")

__device__ __forceinline__ void mma_f16_cg2(uint32_t d, uint64_t ad, uint64_t bd,
                                            uint32_t idesc, uint32_t en) {
    asm volatile("{\n\t.reg .pred p;\n\t"
        "setp.ne.u32 p, %6, 0;\n\t"
        "tcgen05.mma.cta_group::2.kind::f16 [%0], %1, %2, %3, "
        "{%4, %4, %4, %4, %4, %4, %4, %4}, p;\n\t}"
        :: "r"(d), "l"(ad), "l"(bd), "r"(idesc), "r"(0u), "r"(0u), "r"(en)
        : "memory");
}

#define COMMIT_MC_CG2(bar)                                                           \
    asm volatile("tcgen05.commit.cta_group::2.mbarrier::arrive::one.shared::cluster" \
        ".multicast::cluster.b64 [%0], %1;" :: "r"(bar), "h"((uint16_t)0x3) : "memory")

#define LDTM_X32(r, addr)                                                            \
    asm volatile("tcgen05.ld.sync.aligned.32x32b.x32.b32 "                           \
        "{%0, %1, %2, %3, %4, %5, %6, %7, "                                          \
        " %8, %9, %10, %11, %12, %13, %14, %15, "                                    \
        " %16, %17, %18, %19, %20, %21, %22, %23, "                                  \
        " %24, %25, %26, %27, %28, %29, %30, %31}, [%32];"                           \
        : "=r"((r)[0]),  "=r"((r)[1]),  "=r"((r)[2]),  "=r"((r)[3]),                 \
          "=r"((r)[4]),  "=r"((r)[5]),  "=r"((r)[6]),  "=r"((r)[7]),                 \
          "=r"((r)[8]),  "=r"((r)[9]),  "=r"((r)[10]), "=r"((r)[11]),                \
          "=r"((r)[12]), "=r"((r)[13]), "=r"((r)[14]), "=r"((r)[15]),                \
          "=r"((r)[16]), "=r"((r)[17]), "=r"((r)[18]), "=r"((r)[19]),                \
          "=r"((r)[20]), "=r"((r)[21]), "=r"((r)[22]), "=r"((r)[23]),                \
          "=r"((r)[24]), "=r"((r)[25]), "=r"((r)[26]), "=r"((r)[27]),                \
          "=r"((r)[28]), "=r"((r)[29]), "=r"((r)[30]), "=r"((r)[31])                 \
        : "r"(addr))
#endif  // TC_OK

__global__ void __launch_bounds__(320, 1) __cluster_dims__(2, 1, 1) rbm_gemm_tc(
    const float* __restrict__ bias, float* __restrict__ C,
    const __grid_constant__ CUtensorMap tmaA,
    const __grid_constant__ CUtensorMap tmaB) {
#if TC_OK
    extern __shared__ char smem[];
    uint32_t sb = smem_u32(smem);
    int tid = threadIdx.x, wid = tid >> 5, lid = tid & 31;
    uint32_t rank;
    asm("mov.u32 %0, %%cluster_ctarank;" : "=r"(rank));
    int cluster_id = blockIdx.x >> 1;
    int ntiles = (NTILES - cluster_id + NCLUSTERS - 1) / NCLUSTERS;

    if (wid == 4) {
        asm volatile("tcgen05.alloc.cta_group::2.sync.aligned.shared::cta.b32 [%0], %1;"
                     :: "r"(sb + OFF_TMEM), "r"(512u) : "memory");
        asm volatile("tcgen05.relinquish_alloc_permit.cta_group::2.sync.aligned;");
    }
    if (tid == 0) {
#pragma unroll
        for (int s = 0; s < STAGES; s++) {
            MBAR_INIT(sb + OFF_FULL(s), 1);
            MBAR_INIT(sb + OFF_FREE(s), 1);
        }
        MBAR_INIT(sb + OFF_DONE(0), 1);
        MBAR_INIT(sb + OFF_DONE(1), 1);
        MBAR_INIT(sb + OFF_EPI(0), 2);
        MBAR_INIT(sb + OFF_EPI(1), 2);
    }
    __syncthreads();
    CLUSTER_SYNC();

    uint32_t tmem_base;
    asm volatile("ld.shared.b32 %0, [%1];" : "=r"(tmem_base) : "r"(sb + OFF_TMEM));

    if (wid == 4 && lid == 0) {
        // ---- Producer (both ranks): stream ALL tiles' k-blocks, ring never drains
        int s = 0, ph = 1;
        for (int t = 0; t < ntiles; t++) {
            int tile_id = cluster_id + t * NCLUSTERS;
            int m0 = (tile_id >> 4) * 256 + (int)rank * BM;
            int n0 = (tile_id & 15) * 256 + (int)rank * BNH;
            for (int kb = 0; kb < NKB; kb++) {
                MBAR_WAIT_RELAXED(sb + OFF_FREE(s), (uint32_t)ph);
                if (rank == 0)
                    MBAR_EXPECT_TX(sb + OFF_FULL(s), (uint32_t)FULL_TX_BYTES);
                uint32_t da = sb + SMEM_TILE0 + s * STAGE_BYTES;
                uint32_t db = da + STAGE_A_BYTES;
                int k0 = kb * BK;
                TMA_LOAD_2D_CG2(da, (const void*)&tmaA, k0, m0, sb + OFF_FULL(s));
                TMA_LOAD_2D_CG2(db, (const void*)&tmaB, k0, n0, sb + OFF_FULL(s));
                if (++s == STAGES) { s = 0; ph ^= 1; }
            }
        }
    } else if (wid == 5 && lid == 0 && rank == 0) {
        // ---- Leader MMA issuer
        int s = 0, ph = 0;
        for (int t = 0; t < ntiles; t++) {
            int b = t & 1, u = t >> 1;
            if (t >= 2)
                MBAR_WAIT(sb + OFF_EPI(b), (uint32_t)((u & 1) ^ 1));
            uint32_t dbuf = tmem_base + (uint32_t)b * 256;
            for (int kb = 0; kb < NKB; kb++) {
                MBAR_WAIT(sb + OFF_FULL(s), (uint32_t)ph);
                uint32_t sa = sb + SMEM_TILE0 + s * STAGE_BYTES;
                uint64_t ad = make_desc(sa);
                uint64_t bd = make_desc(sa + STAGE_A_BYTES);
                mma_f16_cg2(dbuf, ad,     bd,     IDESC, (kb > 0) ? 1u : 0u);
                mma_f16_cg2(dbuf, ad + 2, bd + 2, IDESC, 1u);
                mma_f16_cg2(dbuf, ad + 4, bd + 4, IDESC, 1u);
                mma_f16_cg2(dbuf, ad + 6, bd + 6, IDESC, 1u);
                COMMIT_MC_CG2(sb + OFF_FREE(s));
                if (++s == STAGES) { s = 0; ph ^= 1; }
            }
            COMMIT_MC_CG2(sb + OFF_DONE(b));
        }
    }

    if (wid < 4 || wid >= 6) {
        // ---- Epilogue: 8 warps. Group lo (wid 0-3) = cols [0,128),
        //      group hi (wid 6-9) = cols [128,256). Subpartition = wid&3.
        int cbase = (wid < 4) ? 0 : 128;
        int sub = wid & 3;
        for (int t = 0; t < ntiles; t++) {
            int b = t & 1, u = t >> 1;
            int tile_id = cluster_id + t * NCLUSTERS;
            MBAR_WAIT(sb + OFF_DONE(b), (uint32_t)(u & 1));
            asm volatile("tcgen05.fence::after_thread_sync;" ::: "memory");
            int row = (tile_id >> 4) * 256 + (int)rank * BM + sub * 32 + lid;
            int col0g = (tile_id & 15) * 256;
            float* crow = C + (size_t)row * NDIM + col0g;
            const float* brow = bias + col0g;
            uint32_t dbuf = tmem_base + (uint32_t)b * 256;
#pragma unroll
            for (int cc = 0; cc < 128; cc += 32) {
                int c0 = cbase + cc;
                uint32_t r[32];
                LDTM_X32(r, dbuf + c0);
                asm volatile("tcgen05.wait::ld.sync.aligned;" ::: "memory");
                float v[32];
#pragma unroll
                for (int i = 0; i < 32; i++) {
                    float z = __uint_as_float(r[i]) + __ldg(&brow[c0 + i]);
                    v[i] = sigmoidf_fast(z);
                }
#pragma unroll
                for (int q = 0; q < 8; q++) {
                    float4 o = make_float4(v[4 * q], v[4 * q + 1],
                                           v[4 * q + 2], v[4 * q + 3]);
                    reinterpret_cast<float4*>(crow + c0)[q] = o;
                }
            }
            asm volatile("tcgen05.fence::before_thread_sync;" ::: "memory");
            asm volatile("bar.sync 1, 256;" ::: "memory");   // 8 epi warps of this CTA
            if (tid == 0)
                MBAR_ARRIVE_LEADER(sb + OFF_EPI(b));          // 2 arrivals: one per CTA
        }
    }

    __syncthreads();
    if (wid == 4) {
        asm volatile("tcgen05.dealloc.cta_group::2.sync.aligned.b32 %0, %1;"
                     :: "r"(tmem_base), "r"(512u));
    }
    CLUSTER_SYNC();
#endif  // TC_OK
}

// ---------------------------------------------------------------------------
// Host launch
// ---------------------------------------------------------------------------
typedef CUresult (*PFN_encodeTiled)(
    CUtensorMap*, CUtensorMapDataType, cuuint32_t, void*,
    const cuuint64_t*, const cuuint64_t*, const cuuint32_t*, const cuuint32_t*,
    CUtensorMapInterleave, CUtensorMapSwizzle, CUtensorMapL2promotion,
    CUtensorMapFloatOOBfill);

extern "C" void kernel_launch(void* const* d_in, const int* in_sizes, int n_in,
                              void* d_out, int out_size) {
    const float* X    = (const float*)d_in[0];
    const float* W    = (const float*)d_in[1];
    const float* bias = (const float*)d_in[2];
    float* C = (float*)d_out;

    void *xh_ptr = nullptr, *wth_ptr = nullptr;
    cudaGetSymbolAddress(&xh_ptr, g_Xh);
    cudaGetSymbolAddress(&wth_ptr, g_Wth);

    convert_all_kernel<<<XBLKS + WBLKS, 256>>>(X, W);

    PFN_encodeTiled encode = nullptr;
    cudaDriverEntryPointQueryResult qr;
    cudaGetDriverEntryPointByVersion("cuTensorMapEncodeTiled", (void**)&encode,
                                     12000, cudaEnableDefault, &qr);

    CUtensorMap tmaA, tmaB;
    if (encode) {
        cuuint64_t dimsA[2]   = {KDIM, MDIM};
        cuuint64_t strA[1]    = {(cuuint64_t)KDIM * sizeof(__half)};
        cuuint32_t boxA[2]    = {BK, BM};
        cuuint32_t es[2]      = {1, 1};
        encode(&tmaA, CU_TENSOR_MAP_DATA_TYPE_FLOAT16, 2, xh_ptr,
               dimsA, strA, boxA, es,
               CU_TENSOR_MAP_INTERLEAVE_NONE, CU_TENSOR_MAP_SWIZZLE_128B,
               CU_TENSOR_MAP_L2_PROMOTION_L2_128B, CU_TENSOR_MAP_FLOAT_OOB_FILL_NONE);
        cuuint64_t dimsB[2]   = {KDIM, NDIM};
        cuuint64_t strB[1]    = {(cuuint64_t)KDIM * sizeof(__half)};
        cuuint32_t boxB[2]    = {BK, BNH};
        encode(&tmaB, CU_TENSOR_MAP_DATA_TYPE_FLOAT16, 2, wth_ptr,
               dimsB, strB, boxB, es,
               CU_TENSOR_MAP_INTERLEAVE_NONE, CU_TENSOR_MAP_SWIZZLE_128B,
               CU_TENSOR_MAP_L2_PROMOTION_L2_128B, CU_TENSOR_MAP_FLOAT_OOB_FILL_NONE);
    }

    cudaFuncSetAttribute(rbm_gemm_tc,
                         cudaFuncAttributeMaxDynamicSharedMemorySize, TC_SMEM_TOTAL);
    // Persistent: 148 CTAs = 74 clusters of 2
    rbm_gemm_tc<<<dim3(2 * NCLUSTERS, 1), 320, TC_SMEM_TOTAL>>>(bias, C, tmaA, tmaB);
}